// round 12
// baseline (speedup 1.0000x reference)
#include <cuda_runtime.h>
#include <cstdint>

#define T_STEPS 512
#define BATCH   512
#define SDIM    64
#define HID     128
#define ADIM    10

#define NCTA    128
#define NTHR    512
#define CLUSTER 8

// float offsets within dynamic smem
#define OFF_MBAR 0       // 2 u64 mbarriers (A at +0, B at +8 bytes)
#define OFF_BIAS 8       // 64 u64: [layer(2)][jl(16)][pr(2)]
#define OFF_WO   136     // 640 u64: [j(128)][ap(5)]
#define OFF_WA   1416    // 12288 floats
#define OFF_WB   13704   // 16384 floats
#define OFF_R0   30088   // 2 bufs x 4096 floats: h0 [jp(64)][b(32)][2]
#define OFF_R1   38280   // 2 bufs x 4096 floats: h1
#define OFF_X    46472   // 2 bufs x 2048 floats: x  [kp(32)][b(32)][2]
#define OFF_STA  50568   // 2 bufs x 512 floats staging for A pushes
#define OFF_STB  51592   // 2 bufs x 512 floats staging for B pushes
#define SMEM_FLOATS 52616
#define SMEM_BYTES (SMEM_FLOATS*4)   // 210464

typedef unsigned long long u64;
typedef unsigned int u32;

__device__ __forceinline__ float tanh_fast(float v) {
    float r; asm("tanh.approx.f32 %0, %1;" : "=f"(r) : "f"(v)); return r;
}
__device__ __forceinline__ float sigmoid_fast(float v) {
    return 0.5f * tanh_fast(0.5f * v) + 0.5f;
}
__device__ __forceinline__ u64 ffma2(u64 a, u64 b, u64 c) {
    u64 d; asm("fma.rn.f32x2 %0, %1, %2, %3;" : "=l"(d) : "l"(a), "l"(b), "l"(c)); return d;
}
__device__ __forceinline__ u64 pack2(float lo, float hi) {
    u64 d; asm("mov.b64 %0, {%1, %2};" : "=l"(d) : "f"(lo), "f"(hi)); return d;
}
__device__ __forceinline__ void unpack2(u64 v, float& lo, float& hi) {
    asm("mov.b64 {%0, %1}, %2;" : "=f"(lo), "=f"(hi) : "l"(v));
}
__device__ __forceinline__ u32 smem_u32(const void* p) {
    u32 a; asm("{ .reg .u64 t; cvta.to.shared.u64 t, %1; cvt.u32.u64 %0, t; }" : "=r"(a) : "l"(p));
    return a;
}
__device__ __forceinline__ void cluster_sync() {
    asm volatile("barrier.cluster.arrive.aligned;" ::: "memory");
    asm volatile("barrier.cluster.wait.aligned;"   ::: "memory");
}
__device__ __forceinline__ bool elect1() {
    u32 p; asm volatile("{ .reg .pred p; elect.sync _|p, 0xFFFFFFFF; selp.b32 %0, 1, 0, p; }"
                        : "=r"(p)); return p != 0;
}
__device__ __forceinline__ void mbar_wait(u32 mb, u32 parity) {
    asm volatile(
        "{ .reg .pred P;\n\t"
        "W%=: mbarrier.try_wait.parity.acquire.cluster.shared::cta.b64 P, [%0], %1, 0x989680;\n\t"
        "@P bra D%=;\n\t"
        "bra W%=;\n\t"
        "D%=: }"
        :: "r"(mb), "r"(parity) : "memory");
}
__device__ __forceinline__ void mbar_expect(u32 mb, u32 bytes) {
    asm volatile("mbarrier.arrive.expect_tx.shared.b64 _, [%0], %1;"
                 :: "r"(mb), "r"(bytes) : "memory");
}
// Bulk-push 256B (one warp's h pairs) from local staging to the same region
// slot of all 8 cluster CTAs, signaling each CTA's mbarrier (+256 tx bytes).
__device__ __forceinline__ void push_bulk(u32 dst_local, u32 src_local, u32 mb_local) {
    asm volatile("fence.proxy.async.shared::cta;" ::: "memory");
    #pragma unroll
    for (int r = 0; r < CLUSTER; ++r) {
        u32 d, m;
        asm("mapa.shared::cluster.u32 %0, %1, %2;" : "=r"(d) : "r"(dst_local), "r"(r));
        asm("mapa.shared::cluster.u32 %0, %1, %2;" : "=r"(m) : "r"(mb_local), "r"(r));
        asm volatile(
            "cp.async.bulk.shared::cluster.shared::cta.mbarrier::complete_tx::bytes "
            "[%0], [%1], 256, [%2];"
            :: "r"(d), "r"(src_local), "r"(m) : "memory");
    }
}

__device__ __forceinline__ float lstm_epi(u64 aif, u64 ago, float& c) {
    float ai, af, ag, ao;
    unpack2(aif, ai, af);
    unpack2(ago, ag, ao);
    float iG = sigmoid_fast(ai), fG = sigmoid_fast(af);
    float gG = tanh_fast(ag),    oG = sigmoid_fast(ao);
    c = fG * c + iG * gG;
    return oG * tanh_fast(c);
}

// GEMM block: KP k-pairs. Weights at wbase: per kp, 64B = u64 gate-pairs
// [k0: j0if j0go j1if j1go][k1: ...]. x at xbase + b*8.
template<int KP>
__device__ __forceinline__ void gemm_blk(u32 wbase, u32 xbase,
                                         u64& a0, u64& a1, u64& a2, u64& a3)
{
    #pragma unroll 4
    for (int kp = 0; kp < KP; ++kp) {
        float x0, x1;
        asm("ld.shared.v2.f32 {%0,%1}, [%2];" : "=f"(x0), "=f"(x1) : "r"(xbase + kp*256));
        u64 X0 = pack2(x0, x0), X1 = pack2(x1, x1);
        u64 wa0, wa1, wb0, wb1, wc0, wc1, wd0, wd1;
        asm("ld.shared.v2.b64 {%0,%1}, [%2];" : "=l"(wa0), "=l"(wa1) : "r"(wbase + kp*64));
        asm("ld.shared.v2.b64 {%0,%1}, [%2];" : "=l"(wb0), "=l"(wb1) : "r"(wbase + kp*64 + 16));
        asm("ld.shared.v2.b64 {%0,%1}, [%2];" : "=l"(wc0), "=l"(wc1) : "r"(wbase + kp*64 + 32));
        asm("ld.shared.v2.b64 {%0,%1}, [%2];" : "=l"(wd0), "=l"(wd1) : "r"(wbase + kp*64 + 48));
        a0 = ffma2(wa0, X0, a0);  a1 = ffma2(wa1, X0, a1);
        a2 = ffma2(wb0, X0, a2);  a3 = ffma2(wb1, X0, a3);
        a0 = ffma2(wc0, X1, a0);  a1 = ffma2(wc1, X1, a1);
        a2 = ffma2(wd0, X1, a2);  a3 = ffma2(wd1, X1, a3);
    }
}

__global__ void __cluster_dims__(CLUSTER, 1, 1) __launch_bounds__(NTHR, 1)
lstm_ws(const float* __restrict__ x,
        const float* __restrict__ W_ih0, const float* __restrict__ W_hh0,
        const float* __restrict__ b_ih0, const float* __restrict__ b_hh0,
        const float* __restrict__ W_ih1, const float* __restrict__ W_hh1,
        const float* __restrict__ b_ih1, const float* __restrict__ b_hh1,
        const float* __restrict__ W_out, const float* __restrict__ b_out,
        float* __restrict__ out)
{
    extern __shared__ float smem[];
    const u32 sb  = smem_u32(smem);
    const int tid = threadIdx.x;
    const int bid = blockIdx.x;
    const int hs  = bid & (CLUSTER - 1);   // hidden slice = cluster rank
    const int bs  = bid >> 3;              // batch slice (shared by cluster)
    const int j0  = hs * 16;
    const int b0  = bs * 32;
    const int b   = tid & 31;              // lane = batch
    const int wid = tid >> 5;              // 16 warps
    const int lw  = wid & 7;               // warp index within group (j-pair)

    const u32 mbA = sb + OFF_MBAR * 4;
    const u32 mbB = sb + OFF_MBAR * 4 + 8;

    // ---- weights layer0 -> smem (interleaved gate-pair layout) ----
    for (int idx = tid; idx < 12288; idx += NTHR) {
        int p  = idx & 1, pr = (idx >> 1) & 1, jl = (idx >> 2) & 1, kk = (idx >> 3) & 1;
        int rest = idx >> 4;
        int kp = rest % 96, jp = rest / 96;
        int k = kp * 2 + kk;
        int gate = pr * 2 + p;
        int row = gate * HID + j0 + jp * 2 + jl;
        smem[OFF_WA + idx] = (k < HID) ? W_hh0[row * HID + k]
                                       : W_ih0[row * SDIM + (k - HID)];
    }
    // ---- weights layer1 ----
    for (int idx = tid; idx < 16384; idx += NTHR) {
        int p  = idx & 1, pr = (idx >> 1) & 1, jl = (idx >> 2) & 1, kk = (idx >> 3) & 1;
        int rest = idx >> 4;
        int kp = rest % 128, jp = rest / 128;
        int k = kp * 2 + kk;
        int gate = pr * 2 + p;
        int row = gate * HID + j0 + jp * 2 + jl;
        smem[OFF_WB + idx] = (k < HID) ? W_ih1[row * HID + k]
                                       : W_hh1[row * HID + (k - HID)];
    }
    // ---- biases ----
    if (tid < 64) {
        int layer = tid >> 5, r = tid & 31, jl = r >> 1, pr = r & 1;
        int jg = j0 + jl;
        int glo = pr * 2, ghi = pr * 2 + 1;
        float lo, hi;
        if (layer == 0) {
            lo = b_ih0[glo*HID + jg] + b_hh0[glo*HID + jg];
            hi = b_ih0[ghi*HID + jg] + b_hh0[ghi*HID + jg];
        } else {
            lo = b_ih1[glo*HID + jg] + b_hh1[glo*HID + jg];
            hi = b_ih1[ghi*HID + jg] + b_hh1[ghi*HID + jg];
        }
        ((u64*)(smem + OFF_BIAS))[layer*32 + jl*2 + pr] = pack2(lo, hi);
    }
    // ---- head weights: [j][ap] u64 ----
    for (int idx = tid; idx < 640; idx += NTHR) {
        int j = idx / 5, ap = idx - j*5;
        ((u64*)(smem + OFF_WO))[idx] = pack2(W_out[(2*ap)*HID + j], W_out[(2*ap+1)*HID + j]);
    }
    // ---- zero buf1 of R0/R1 (h0(-1) = h1(-1) = 0) ----
    for (int idx = tid; idx < 4096; idx += NTHR) {
        smem[OFF_R0 + 4096 + idx] = 0.0f;
        smem[OFF_R1 + 4096 + idx] = 0.0f;
    }
    // ---- stage x(0) -> xbuf0 (warps 0-7), x(1) -> xbuf1 (warps 8-15) ----
    {
        int tt = wid >> 3;
        const float4* xp = (const float4*)&x[((size_t)tt*BATCH + b0 + b)*SDIM + lw*8];
        float4 xa = xp[0], xb2 = xp[1];
        float* xd = smem + OFF_X + tt*2048 + ((lw*4)*32 + b)*2;
        *(float2*)(xd      ) = make_float2(xa.x, xa.y);
        *(float2*)(xd +  64) = make_float2(xa.z, xa.w);
        *(float2*)(xd + 128) = make_float2(xb2.x, xb2.y);
        *(float2*)(xd + 192) = make_float2(xb2.z, xb2.w);
    }
    // ---- mbarrier init (count = 1: tid0's expect_tx arrival per phase) ----
    if (tid == 0) {
        asm volatile("mbarrier.init.shared.b64 [%0], 1;" :: "r"(mbA) : "memory");
        asm volatile("mbarrier.init.shared.b64 [%0], 1;" :: "r"(mbB) : "memory");
    }
    __syncthreads();
    cluster_sync();   // peers' mbars + buffers ready before any pushes
    if (tid == 0) {
        mbar_expect(mbA, 16384);   // phase 0 of A
        mbar_expect(mbB, 16384);   // phase 0 of B
    }

    const bool isL1 = (wid < 8);
    const u64* biasU = (const u64*)(smem + OFF_BIAS);
    const int bsel = isL1 ? 32 : 0;
    const u64 bR0 = biasU[bsel + lw*4 + 0], bR1 = biasU[bsel + lw*4 + 1];
    const u64 bR2 = biasU[bsel + lw*4 + 2], bR3 = biasU[bsel + lw*4 + 3];
    const u64 houtb = (wid < 5) ? pack2(b_out[wid*2], b_out[wid*2+1]) : 0ull;

    const u32 wbase  = isL1 ? (sb + OFF_WB*4 + lw*8192)   // 128 kp x 64B
                            : (sb + OFF_WA*4 + lw*6144);  // 96 kp x 64B
    const u32 lane8  = b * 8;
    const u32 regOff = (u32)(hs*8 + lw) * 256;            // warp's 256B slot

    float cA = 0.f, cB = 0.f;                             // cell state (2 j's)

    // ---- prologue (L0 group only): L0(0) from [h0(-1)=0 | x(0)], push A(0) ----
    if (!isL1) {
        u64 a0 = bR0, a1 = bR1, a2 = bR2, a3 = bR3;
        gemm_blk<64>(wbase,        sb + (OFF_R0 + 4096)*4 + lane8, a0, a1, a2, a3);
        gemm_blk<32>(wbase + 4096, sb + OFF_X*4 + lane8,           a0, a1, a2, a3);
        float h00 = lstm_epi(a0, a1, cA);
        float h01 = lstm_epi(a2, a3, cB);
        u32 stg = sb + (OFF_STA + 0*512 + lw*64)*4;
        asm volatile("st.shared.b64 [%0], %1;" :: "r"(stg + lane8), "l"(pack2(h00, h01)) : "memory");
        __syncwarp();
        if (elect1())
            push_bulk(sb + OFF_R0*4 + regOff, stg, mbA);   // h0(0) -> r0 buf0
    }

    // ---- main loop: two concurrent warp groups ----
    for (int t = 0; t < T_STEPS; ++t) {
        const u32 par    = (u32)(t & 1);
        const u32 r0cur  = sb + (OFF_R0 + (t&1)*4096)*4;       // h0(t)
        const u32 r0next = sb + (OFF_R0 + ((t+1)&1)*4096)*4;   // h0(t+1) dest
        const u32 r1prev = sb + (OFF_R1 + ((t+1)&1)*4096)*4;   // h1(t-1)
        const u32 r1cur  = sb + (OFF_R1 + (t&1)*4096)*4;       // h1(t) dest
        const u32 xnext  = sb + (OFF_X  + ((t+1)&1)*2048)*4;   // x(t+1)

        if (isL1) {
            // ================= L1 group =================
            mbar_wait(mbA, par);                  // h0(t) complete locally
            if (tid == 0 && t + 1 < T_STEPS) mbar_expect(mbA, 16384);

            // L1(t): [h0(t) | h1(t-1)]
            u64 a0 = bR0, a1 = bR1, a2 = bR2, a3 = bR3;
            gemm_blk<64>(wbase,        r0cur  + lane8, a0, a1, a2, a3);
            gemm_blk<64>(wbase + 4096, r1prev + lane8, a0, a1, a2, a3);
            float h10 = lstm_epi(a0, a1, cA);
            float h11 = lstm_epi(a2, a3, cB);
            u32 stg = sb + (OFF_STB + par*512 + lw*64)*4;
            asm volatile("st.shared.b64 [%0], %1;" :: "r"(stg + lane8), "l"(pack2(h10, h11)) : "memory");
            __syncwarp();
            if (elect1())
                push_bulk(r1cur + regOff, stg, mbB);

            mbar_wait(mbB, par);                  // h1(t) complete locally
            if (tid == 0 && t + 1 < T_STEPS) mbar_expect(mbB, 16384);

            // head(t): out = tanh(h1(t) @ W_out^T + b_out)
            if (wid < 5) {
                u64 acc = houtb;
                const u32 wo = sb + OFF_WO*4 + wid*8;
                #pragma unroll 8
                for (int kp = 0; kp < 64; ++kp) {
                    float h0v, h1v;
                    asm("ld.shared.v2.f32 {%0,%1}, [%2];" : "=f"(h0v), "=f"(h1v)
                        : "r"(r1cur + lane8 + kp*256));
                    u64 w0, w1;
                    asm("ld.shared.b64 %0, [%1];" : "=l"(w0) : "r"(wo + kp*80));
                    asm("ld.shared.b64 %0, [%1];" : "=l"(w1) : "r"(wo + kp*80 + 40));
                    acc = ffma2(w0, pack2(h0v, h0v), acc);
                    acc = ffma2(w1, pack2(h1v, h1v), acc);
                }
                float o0, o1; unpack2(acc, o0, o1);
                float2 ov = make_float2(tanh_fast(o0), tanh_fast(o1));
                *(float2*)&out[((size_t)t*BATCH + b0 + b)*ADIM + wid*2] = ov;
            }
        } else {
            // ================= L0 group =================
            // prefetch x(t+2) (no dependence on barriers)
            float4 xa, xb2;
            if (t + 2 < T_STEPS) {
                const float4* xp = (const float4*)&x[((size_t)(t+2)*BATCH + b0 + b)*SDIM + lw*8];
                xa = xp[0]; xb2 = xp[1];
            }

            // Coupling: before pushing A(t+1) (which lets peers start step t+1
            // overwrites), ensure phase B(t-1) done -> all CTAs' L1(t-1) reads
            // of the double-buffered regions have completed.
            if (t > 0) mbar_wait(mbB, (u32)((t-1) & 1));
            mbar_wait(mbA, par);                  // h0(t) complete locally

            if (t + 1 < T_STEPS) {
                // L0(t+1): [h0(t) | x(t+1)]
                u64 a0 = bR0, a1 = bR1, a2 = bR2, a3 = bR3;
                gemm_blk<64>(wbase,        r0cur + lane8, a0, a1, a2, a3);
                gemm_blk<32>(wbase + 4096, xnext + lane8, a0, a1, a2, a3);
                float h00 = lstm_epi(a0, a1, cA);
                float h01 = lstm_epi(a2, a3, cB);
                u32 stg = sb + (OFF_STA + ((t+1)&1)*512 + lw*64)*4;
                asm volatile("st.shared.b64 [%0], %1;" :: "r"(stg + lane8), "l"(pack2(h00, h01)) : "memory");
                __syncwarp();
                if (elect1())
                    push_bulk(r0next + regOff, stg, mbA);
            }

            // stage x(t+2) into xbuf[t&1] (x(t) is dead; local-only buffer)
            if (t + 2 < T_STEPS) {
                float* xd = smem + OFF_X + (t&1)*2048 + ((lw*4)*32 + b)*2;
                *(float2*)(xd      ) = make_float2(xa.x, xa.y);
                *(float2*)(xd +  64) = make_float2(xa.z, xa.w);
                *(float2*)(xd + 128) = make_float2(xb2.x, xb2.y);
                *(float2*)(xd + 192) = make_float2(xb2.z, xb2.w);
            }
            // group barrier: x staging visible to all L0 warps next iter
            asm volatile("bar.sync 1, 256;" ::: "memory");
        }
    }

    cluster_sync();   // all deliveries drained before any CTA exits
}

extern "C" void kernel_launch(void* const* d_in, const int* in_sizes, int n_in,
                              void* d_out, int out_size)
{
    const float* x    = (const float*)d_in[0];
    const float* Wih0 = (const float*)d_in[1];
    const float* Whh0 = (const float*)d_in[2];
    const float* bih0 = (const float*)d_in[3];
    const float* bhh0 = (const float*)d_in[4];
    const float* Wih1 = (const float*)d_in[5];
    const float* Whh1 = (const float*)d_in[6];
    const float* bih1 = (const float*)d_in[7];
    const float* bhh1 = (const float*)d_in[8];
    const float* Wout = (const float*)d_in[9];
    const float* bout = (const float*)d_in[10];
    float* out = (float*)d_out;

    cudaFuncSetAttribute(lstm_ws,
                         cudaFuncAttributeMaxDynamicSharedMemorySize, SMEM_BYTES);

    lstm_ws<<<NCTA, NTHR, SMEM_BYTES>>>(
        x, Wih0, Whh0, bih0, bhh0, Wih1, Whh1, bih1, bhh1, Wout, bout, out);
}

// round 15
// speedup vs baseline: 1.0069x; 1.0069x over previous
#include <cuda_runtime.h>
#include <cstdint>

#define T_STEPS 512
#define BATCH   512
#define SDIM    64
#define HID     128
#define ADIM    10

#define NCTA    128
#define NTHR    512
#define CLUSTER 8

// float offsets within dynamic smem
#define OFF_MBAR 0       // 1 u64 mbarrier
#define OFF_BIAS 8       // 64 u64: [layer(2)][jl(16)][pr(2)]
#define OFF_WO   136     // 640 u64: [j(128)][ap(5)]
#define OFF_WA   1416    // 12288 floats
#define OFF_WB   13704   // 16384 floats
#define OFF_R0   30088   // 2 bufs x 4096 floats: h0 [jp(64)][b(32)][2]
#define OFF_R1   38280   // 2 bufs x 4096 floats: h1
#define OFF_X    46472   // 2 bufs x 2048 floats: x  [kp(32)][b(32)][2]
#define OFF_STA  50568   // 2 bufs x 512 floats staging for h0 pushes
#define OFF_STB  51592   // 2 bufs x 512 floats staging for h1 pushes
#define SMEM_FLOATS 52616
#define SMEM_BYTES (SMEM_FLOATS*4)   // 210464

typedef unsigned long long u64;
typedef unsigned int u32;

__device__ __forceinline__ float tanh_fast(float v) {
    float r; asm("tanh.approx.f32 %0, %1;" : "=f"(r) : "f"(v)); return r;
}
__device__ __forceinline__ float sigmoid_fast(float v) {
    return 0.5f * tanh_fast(0.5f * v) + 0.5f;
}
__device__ __forceinline__ u64 ffma2(u64 a, u64 b, u64 c) {
    u64 d; asm("fma.rn.f32x2 %0, %1, %2, %3;" : "=l"(d) : "l"(a), "l"(b), "l"(c)); return d;
}
__device__ __forceinline__ u64 pack2(float lo, float hi) {
    u64 d; asm("mov.b64 %0, {%1, %2};" : "=l"(d) : "f"(lo), "f"(hi)); return d;
}
__device__ __forceinline__ void unpack2(u64 v, float& lo, float& hi) {
    asm("mov.b64 {%0, %1}, %2;" : "=f"(lo), "=f"(hi) : "l"(v));
}
__device__ __forceinline__ u32 smem_u32(const void* p) {
    u32 a; asm("{ .reg .u64 t; cvta.to.shared.u64 t, %1; cvt.u32.u64 %0, t; }" : "=r"(a) : "l"(p));
    return a;
}
__device__ __forceinline__ void cluster_sync() {
    asm volatile("barrier.cluster.arrive.aligned;" ::: "memory");
    asm volatile("barrier.cluster.wait.aligned;"   ::: "memory");
}
__device__ __forceinline__ bool elect1() {
    u32 p; asm volatile("{ .reg .pred p; elect.sync _|p, 0xFFFFFFFF; selp.b32 %0, 1, 0, p; }"
                        : "=r"(p)); return p != 0;
}
__device__ __forceinline__ void mbar_wait(u32 mb, u32 parity) {
    asm volatile(
        "{ .reg .pred P;\n\t"
        "W%=: mbarrier.try_wait.parity.acquire.cluster.shared::cta.b64 P, [%0], %1, 0x989680;\n\t"
        "@P bra D%=;\n\t"
        "bra W%=;\n\t"
        "D%=: }"
        :: "r"(mb), "r"(parity) : "memory");
}
__device__ __forceinline__ void mbar_expect(u32 mb, u32 bytes) {
    asm volatile("mbarrier.arrive.expect_tx.shared.b64 _, [%0], %1;"
                 :: "r"(mb), "r"(bytes) : "memory");
}
// Bulk-push 256B (one warp's h pairs) from local staging to the same region
// slot of all 8 cluster CTAs, signaling each CTA's mbarrier (+256 tx bytes).
__device__ __forceinline__ void push_bulk(u32 dst_local, u32 src_local, u32 mb_local) {
    asm volatile("fence.proxy.async.shared::cta;" ::: "memory");
    #pragma unroll
    for (int r = 0; r < CLUSTER; ++r) {
        u32 d, m;
        asm("mapa.shared::cluster.u32 %0, %1, %2;" : "=r"(d) : "r"(dst_local), "r"(r));
        asm("mapa.shared::cluster.u32 %0, %1, %2;" : "=r"(m) : "r"(mb_local), "r"(r));
        asm volatile(
            "cp.async.bulk.shared::cluster.shared::cta.mbarrier::complete_tx::bytes "
            "[%0], [%1], 256, [%2];"
            :: "r"(d), "r"(src_local), "r"(m) : "memory");
    }
}

__device__ __forceinline__ float lstm_epi(u64 aif, u64 ago, float& c) {
    float ai, af, ag, ao;
    unpack2(aif, ai, af);
    unpack2(ago, ag, ao);
    float iG = sigmoid_fast(ai), fG = sigmoid_fast(af);
    float gG = tanh_fast(ag),    oG = sigmoid_fast(ao);
    c = fG * c + iG * gG;
    return oG * tanh_fast(c);
}

// GEMM block: KP k-pairs. Weights at wbase: per kp, 64B = u64 gate-pairs
// [k0: j0if j0go j1if j1go][k1: ...]. x at xbase + b*8.
template<int KP>
__device__ __forceinline__ void gemm_blk(u32 wbase, u32 xbase,
                                         u64& a0, u64& a1, u64& a2, u64& a3)
{
    #pragma unroll 4
    for (int kp = 0; kp < KP; ++kp) {
        float x0, x1;
        asm("ld.shared.v2.f32 {%0,%1}, [%2];" : "=f"(x0), "=f"(x1) : "r"(xbase + kp*256));
        u64 X0 = pack2(x0, x0), X1 = pack2(x1, x1);
        u64 wa0, wa1, wb0, wb1, wc0, wc1, wd0, wd1;
        asm("ld.shared.v2.b64 {%0,%1}, [%2];" : "=l"(wa0), "=l"(wa1) : "r"(wbase + kp*64));
        asm("ld.shared.v2.b64 {%0,%1}, [%2];" : "=l"(wb0), "=l"(wb1) : "r"(wbase + kp*64 + 16));
        asm("ld.shared.v2.b64 {%0,%1}, [%2];" : "=l"(wc0), "=l"(wc1) : "r"(wbase + kp*64 + 32));
        asm("ld.shared.v2.b64 {%0,%1}, [%2];" : "=l"(wd0), "=l"(wd1) : "r"(wbase + kp*64 + 48));
        a0 = ffma2(wa0, X0, a0);  a1 = ffma2(wa1, X0, a1);
        a2 = ffma2(wb0, X0, a2);  a3 = ffma2(wb1, X0, a3);
        a0 = ffma2(wc0, X1, a0);  a1 = ffma2(wc1, X1, a1);
        a2 = ffma2(wd0, X1, a2);  a3 = ffma2(wd1, X1, a3);
    }
}

__global__ void __cluster_dims__(CLUSTER, 1, 1) __launch_bounds__(NTHR, 1)
lstm_1ph(const float* __restrict__ x,
         const float* __restrict__ W_ih0, const float* __restrict__ W_hh0,
         const float* __restrict__ b_ih0, const float* __restrict__ b_hh0,
         const float* __restrict__ W_ih1, const float* __restrict__ W_hh1,
         const float* __restrict__ b_ih1, const float* __restrict__ b_hh1,
         const float* __restrict__ W_out, const float* __restrict__ b_out,
         float* __restrict__ out)
{
    extern __shared__ float smem[];
    const u32 sb  = smem_u32(smem);
    const int tid = threadIdx.x;
    const int bid = blockIdx.x;
    const int hs  = bid & (CLUSTER - 1);   // hidden slice = cluster rank
    const int bs  = bid >> 3;              // batch slice (shared by cluster)
    const int j0  = hs * 16;
    const int b0  = bs * 32;
    const int b   = tid & 31;              // lane = batch
    const int wid = tid >> 5;              // 16 warps
    const int lw  = wid & 7;               // warp index within group (j-pair)

    const u32 mb = sb + OFF_MBAR * 4;

    // ---- weights layer0 -> smem (interleaved gate-pair layout) ----
    for (int idx = tid; idx < 12288; idx += NTHR) {
        int p  = idx & 1, pr = (idx >> 1) & 1, jl = (idx >> 2) & 1, kk = (idx >> 3) & 1;
        int rest = idx >> 4;
        int kp = rest % 96, jp = rest / 96;
        int k = kp * 2 + kk;
        int gate = pr * 2 + p;
        int row = gate * HID + j0 + jp * 2 + jl;
        smem[OFF_WA + idx] = (k < HID) ? W_hh0[row * HID + k]
                                       : W_ih0[row * SDIM + (k - HID)];
    }
    // ---- weights layer1 ----
    for (int idx = tid; idx < 16384; idx += NTHR) {
        int p  = idx & 1, pr = (idx >> 1) & 1, jl = (idx >> 2) & 1, kk = (idx >> 3) & 1;
        int rest = idx >> 4;
        int kp = rest % 128, jp = rest / 128;
        int k = kp * 2 + kk;
        int gate = pr * 2 + p;
        int row = gate * HID + j0 + jp * 2 + jl;
        smem[OFF_WB + idx] = (k < HID) ? W_ih1[row * HID + k]
                                       : W_hh1[row * HID + (k - HID)];
    }
    // ---- biases ----
    if (tid < 64) {
        int layer = tid >> 5, r = tid & 31, jl = r >> 1, pr = r & 1;
        int jg = j0 + jl;
        int glo = pr * 2, ghi = pr * 2 + 1;
        float lo, hi;
        if (layer == 0) {
            lo = b_ih0[glo*HID + jg] + b_hh0[glo*HID + jg];
            hi = b_ih0[ghi*HID + jg] + b_hh0[ghi*HID + jg];
        } else {
            lo = b_ih1[glo*HID + jg] + b_hh1[glo*HID + jg];
            hi = b_ih1[ghi*HID + jg] + b_hh1[ghi*HID + jg];
        }
        ((u64*)(smem + OFF_BIAS))[layer*32 + jl*2 + pr] = pack2(lo, hi);
    }
    // ---- head weights: [j][ap] u64 ----
    for (int idx = tid; idx < 640; idx += NTHR) {
        int j = idx / 5, ap = idx - j*5;
        ((u64*)(smem + OFF_WO))[idx] = pack2(W_out[(2*ap)*HID + j], W_out[(2*ap+1)*HID + j]);
    }
    // ---- zero buf1 of R0/R1 (h0(-1) source, h1(-1)) ----
    for (int idx = tid; idx < 4096; idx += NTHR) {
        smem[OFF_R0 + 4096 + idx] = 0.0f;
        smem[OFF_R1 + 4096 + idx] = 0.0f;
    }
    // ---- stage x(0) -> xbuf0 (warps 0-7), x(1) -> xbuf1 (warps 8-15) ----
    {
        int tt = wid >> 3;
        const float4* xp = (const float4*)&x[((size_t)tt*BATCH + b0 + b)*SDIM + lw*8];
        float4 xa = xp[0], xb2 = xp[1];
        float* xd = smem + OFF_X + tt*2048 + ((lw*4)*32 + b)*2;
        *(float2*)(xd      ) = make_float2(xa.x, xa.y);
        *(float2*)(xd +  64) = make_float2(xa.z, xa.w);
        *(float2*)(xd + 128) = make_float2(xb2.x, xb2.y);
        *(float2*)(xd + 192) = make_float2(xb2.z, xb2.w);
    }
    // ---- mbarrier init (count = 1: tid0's expect_tx arrival per phase) ----
    if (tid == 0) {
        asm volatile("mbarrier.init.shared.b64 [%0], 1;" :: "r"(mb) : "memory");
    }
    __syncthreads();
    // expect for phase 0 (prologue h0(0) pushes only: 8 CTAs x 8 warps x 256B)
    if (tid == 0) mbar_expect(mb, 16384);
    cluster_sync();   // peers' mbar + buffers ready before any pushes

    const bool isL1 = (wid < 8);
    const u64* biasU = (const u64*)(smem + OFF_BIAS);
    const int bsel = isL1 ? 32 : 0;
    const u64 bR0 = biasU[bsel + lw*4 + 0], bR1 = biasU[bsel + lw*4 + 1];
    const u64 bR2 = biasU[bsel + lw*4 + 2], bR3 = biasU[bsel + lw*4 + 3];
    const u64 houtb = (!isL1 && lw < 5) ? pack2(b_out[lw*2], b_out[lw*2+1]) : 0ull;

    const u32 wbase  = isL1 ? (sb + OFF_WB*4 + lw*8192)   // 128 kp x 64B
                            : (sb + OFF_WA*4 + lw*6144);  // 96 kp x 64B
    const u32 lane8  = b * 8;
    const u32 regOff = (u32)(hs*8 + lw) * 256;            // warp's 256B slot

    float cA = 0.f, cB = 0.f;                             // cell state (2 j's)

    // ---- prologue (L0 group): L0(0) from [h0(-1)=0 (R0 buf1) | x(0) (xbuf0)],
    //      push h0(0) -> R0 buf0 (phase 0) ----
    if (!isL1) {
        u64 a0 = bR0, a1 = bR1, a2 = bR2, a3 = bR3;
        gemm_blk<64>(wbase,        sb + (OFF_R0 + 4096)*4 + lane8, a0, a1, a2, a3);
        gemm_blk<32>(wbase + 4096, sb + OFF_X*4 + lane8,           a0, a1, a2, a3);
        float h00 = lstm_epi(a0, a1, cA);
        float h01 = lstm_epi(a2, a3, cB);
        u32 stg = sb + (OFF_STA + 0*512 + lw*64)*4;
        asm volatile("st.shared.b64 [%0], %1;" :: "r"(stg + lane8), "l"(pack2(h00, h01)) : "memory");
        __syncwarp();
        if (elect1())
            push_bulk(sb + OFF_R0*4 + regOff, stg, mb);
    }

    // ---- main loop: ONE exchange phase per step ----
    // Phase t delivers: h0(t) -> R0[t&1], h1(t-1) -> R1[(t+1)&1]  (phase 0: h0 only)
    for (int t = 0; t < T_STEPS; ++t) {
        const u32 par    = (u32)(t & 1);
        const u32 r0cur  = sb + (OFF_R0 + (t&1)*4096)*4;       // h0(t)
        const u32 r0next = sb + (OFF_R0 + ((t+1)&1)*4096)*4;   // h0(t+1) dest
        const u32 r1prev = sb + (OFF_R1 + ((t+1)&1)*4096)*4;   // h1(t-1)
        const u32 r1cur  = sb + (OFF_R1 + (t&1)*4096)*4;       // h1(t) dest
        const u32 xnext  = sb + (OFF_X  + ((t+1)&1)*2048)*4;   // x(t+1)

        if (isL1) {
            // ================= L1 group =================
            mbar_wait(mb, par);                   // h0(t), h1(t-1) delivered
            if (tid == 0)
                mbar_expect(mb, (t + 1 < T_STEPS) ? 32768u : 16384u);

            // L1(t): [h0(t) | h1(t-1)] -> h1(t)
            u64 a0 = bR0, a1 = bR1, a2 = bR2, a3 = bR3;
            gemm_blk<64>(wbase,        r0cur  + lane8, a0, a1, a2, a3);
            gemm_blk<64>(wbase + 4096, r1prev + lane8, a0, a1, a2, a3);
            float h10 = lstm_epi(a0, a1, cA);
            float h11 = lstm_epi(a2, a3, cB);
            u32 stg = sb + (OFF_STB + par*512 + lw*64)*4;
            asm volatile("st.shared.b64 [%0], %1;" :: "r"(stg + lane8), "l"(pack2(h10, h11)) : "memory");
            __syncwarp();
            if (elect1())
                push_bulk(r1cur + regOff, stg, mb);   // part of phase t+1
        } else {
            // ================= L0 group =================
            // prefetch x(t+2) before the wait (independent of barriers)
            float4 xa, xb2;
            if (t + 2 < T_STEPS) {
                const float4* xp = (const float4*)&x[((size_t)(t+2)*BATCH + b0 + b)*SDIM + lw*8];
                xa = xp[0]; xb2 = xp[1];
            }

            mbar_wait(mb, par);                   // h0(t), h1(t-1) delivered

            // head(t-1): reads h1(t-1) from r1prev. Must precede this group's
            // push (peers' phase-(t+1) pass implies our pushes, hence head done,
            // before anyone overwrites r1prev with h1(t+1)).
            if (t > 0 && lw < 5) {
                u64 acc = houtb;
                const u32 wo = sb + OFF_WO*4 + lw*8;
                #pragma unroll 8
                for (int kp = 0; kp < 64; ++kp) {
                    float h0v, h1v;
                    asm("ld.shared.v2.f32 {%0,%1}, [%2];" : "=f"(h0v), "=f"(h1v)
                        : "r"(r1prev + lane8 + kp*256));
                    u64 w0, w1;
                    asm("ld.shared.b64 %0, [%1];" : "=l"(w0) : "r"(wo + kp*80));
                    asm("ld.shared.b64 %0, [%1];" : "=l"(w1) : "r"(wo + kp*80 + 40));
                    acc = ffma2(w0, pack2(h0v, h0v), acc);
                    acc = ffma2(w1, pack2(h1v, h1v), acc);
                }
                float o0, o1; unpack2(acc, o0, o1);
                float2 ov = make_float2(tanh_fast(o0), tanh_fast(o1));
                *(float2*)&out[((size_t)(t-1)*BATCH + b0 + b)*ADIM + lw*2] = ov;
            }

            if (t + 1 < T_STEPS) {
                // L0(t+1): [h0(t) | x(t+1)] -> h0(t+1)
                u64 a0 = bR0, a1 = bR1, a2 = bR2, a3 = bR3;
                gemm_blk<64>(wbase,        r0cur + lane8, a0, a1, a2, a3);
                gemm_blk<32>(wbase + 4096, xnext + lane8, a0, a1, a2, a3);
                float h00 = lstm_epi(a0, a1, cA);
                float h01 = lstm_epi(a2, a3, cB);
                u32 stg = sb + (OFF_STA + ((t+1)&1)*512 + lw*64)*4;
                asm volatile("st.shared.b64 [%0], %1;" :: "r"(stg + lane8), "l"(pack2(h00, h01)) : "memory");
                __syncwarp();
                if (elect1())
                    push_bulk(r0next + regOff, stg, mb);   // part of phase t+1
            }

            // stage x(t+2) into xbuf[t&1] (x(t) dead; group bar below makes the
            // writes visible to all L0 warps for next iteration, and the bar at
            // the END of the previous iteration made last iter's reads complete
            // before this overwrite)
            if (t + 2 < T_STEPS) {
                float* xd = smem + OFF_X + (t&1)*2048 + ((lw*4)*32 + b)*2;
                *(float2*)(xd      ) = make_float2(xa.x, xa.y);
                *(float2*)(xd +  64) = make_float2(xa.z, xa.w);
                *(float2*)(xd + 128) = make_float2(xb2.x, xb2.y);
                *(float2*)(xd + 192) = make_float2(xb2.z, xb2.w);
            }
            asm volatile("bar.sync 1, 256;" ::: "memory");   // L0-group barrier
        }
    }

    // ---- final head: t = T-1 (phase T delivers h1(T-1) -> R1[(T+1)&1] = buf1) ----
    if (!isL1) {
        mbar_wait(mb, (u32)(T_STEPS & 1));   // phase 512, parity 0
        if (lw < 5) {
            const u32 r1fin = sb + (OFF_R1 + 4096)*4;   // buf1 = h1(511)
            u64 acc = houtb;
            const u32 wo = sb + OFF_WO*4 + lw*8;
            #pragma unroll 8
            for (int kp = 0; kp < 64; ++kp) {
                float h0v, h1v;
                asm("ld.shared.v2.f32 {%0,%1}, [%2];" : "=f"(h0v), "=f"(h1v)
                    : "r"(r1fin + lane8 + kp*256));
                u64 w0, w1;
                asm("ld.shared.b64 %0, [%1];" : "=l"(w0) : "r"(wo + kp*80));
                asm("ld.shared.b64 %0, [%1];" : "=l"(w1) : "r"(wo + kp*80 + 40));
                acc = ffma2(w0, pack2(h0v, h0v), acc);
                acc = ffma2(w1, pack2(h1v, h1v), acc);
            }
            float o0, o1; unpack2(acc, o0, o1);
            float2 ov = make_float2(tanh_fast(o0), tanh_fast(o1));
            *(float2*)&out[((size_t)(T_STEPS-1)*BATCH + b0 + b)*ADIM + lw*2] = ov;
        }
    }

    cluster_sync();   // all deliveries drained before any CTA exits
}

extern "C" void kernel_launch(void* const* d_in, const int* in_sizes, int n_in,
                              void* d_out, int out_size)
{
    const float* x    = (const float*)d_in[0];
    const float* Wih0 = (const float*)d_in[1];
    const float* Whh0 = (const float*)d_in[2];
    const float* bih0 = (const float*)d_in[3];
    const float* bhh0 = (const float*)d_in[4];
    const float* Wih1 = (const float*)d_in[5];
    const float* Whh1 = (const float*)d_in[6];
    const float* bih1 = (const float*)d_in[7];
    const float* bhh1 = (const float*)d_in[8];
    const float* Wout = (const float*)d_in[9];
    const float* bout = (const float*)d_in[10];
    float* out = (float*)d_out;

    cudaFuncSetAttribute(lstm_1ph,
                         cudaFuncAttributeMaxDynamicSharedMemorySize, SMEM_BYTES);

    lstm_1ph<<<NCTA, NTHR, SMEM_BYTES>>>(
        x, Wih0, Whh0, bih0, bhh0, Wih1, Whh1, bih1, bhh1, Wout, bout, out);
}